// round 5
// baseline (speedup 1.0000x reference)
#include <cuda_runtime.h>
#include <cstdint>

#define T_TOK 4096
#define D_MODEL 1024
#define NH 16
#define QKV_N 3072

// Scratch (__device__ globals per allocation rules)
__device__ float g_qkv[T_TOK * QKV_N];      // rounded-tf32 q|k|v
__device__ float g_attn[T_TOK * D_MODEL];   // rounded-tf32 attention out
__device__ float g_xr[T_TOK * D_MODEL];     // rounded inputs
__device__ float g_wqkvr[QKV_N * D_MODEL];
__device__ float g_woutr[D_MODEL * D_MODEL];

// ---------------------------------------------------------------------------
// helpers
// ---------------------------------------------------------------------------
__device__ __forceinline__ uint32_t f2tf(float f) {
    uint32_t u; asm("cvt.rna.tf32.f32 %0, %1;" : "=r"(u) : "f"(f)); return u;
}
__device__ __forceinline__ void cp16(void* smem, const void* gmem) {
    uint32_t s = (uint32_t)__cvta_generic_to_shared(smem);
    asm volatile("cp.async.cg.shared.global [%0], [%1], 16;" :: "r"(s), "l"(gmem));
}
__device__ __forceinline__ void cp_commit() { asm volatile("cp.async.commit_group;"); }
template <int N> __device__ __forceinline__ void cp_wait() {
    asm volatile("cp.async.wait_group %0;" :: "n"(N));
}
// D += A*B, m16n8k8 tf32 (A row-major, B col-major)
__device__ __forceinline__ void mma8(float* c, uint32_t a0, uint32_t a1, uint32_t a2,
                                     uint32_t a3, uint32_t b0, uint32_t b1) {
    asm("mma.sync.aligned.m16n8k8.row.col.f32.tf32.tf32.f32 "
        "{%0,%1,%2,%3}, {%4,%5,%6,%7}, {%8,%9}, {%0,%1,%2,%3};"
        : "+f"(c[0]), "+f"(c[1]), "+f"(c[2]), "+f"(c[3])
        : "r"(a0), "r"(a1), "r"(a2), "r"(a3), "r"(b0), "r"(b1));
}

// ---------------------------------------------------------------------------
// elementwise rna(tf32) rounding
// ---------------------------------------------------------------------------
__global__ void round_k(const float4* __restrict__ in, float4* __restrict__ out, int n4) {
    int i = blockIdx.x * blockDim.x + threadIdx.x;
    if (i >= n4) return;
    float4 v = in[i];
    uint4 o = {f2tf(v.x), f2tf(v.y), f2tf(v.z), f2tf(v.w)};
    out[i] = *reinterpret_cast<float4*>(&o);
}

// ---------------------------------------------------------------------------
// tf32 tensor-core GEMM (NT): unchanged from round 4 (222us, near warp-mma peak)
// ---------------------------------------------------------------------------
#define SA 36
#define GEMM_SMEM (2 * 2 * 128 * SA * 4)

template <bool ROUND_OUT>
__global__ __launch_bounds__(256, 2) void gemm_tf32(const float* __restrict__ A,
                                                    const float* __restrict__ B,
                                                    float* __restrict__ C,
                                                    int M, int N, int K) {
    extern __shared__ float sm[];
    float* Abuf[2] = {sm, sm + 2 * 128 * SA};
    float* Bbuf[2] = {sm + 128 * SA, sm + 3 * 128 * SA};

    const int tid = threadIdx.x;
    const int wid = tid >> 5, lane = tid & 31;
    const int g = lane >> 2, tig = lane & 3;
    const int mW = (wid >> 2) * 64, nW = (wid & 3) * 32;
    const int by = blockIdx.y * 128, bx = blockIdx.x * 128;

    float acc[4][4][4];
#pragma unroll
    for (int a = 0; a < 4; a++)
#pragma unroll
        for (int b = 0; b < 4; b++)
#pragma unroll
            for (int c = 0; c < 4; c++) acc[a][b][c] = 0.f;

    const int nkt = K / 32;

    auto load_tile = [&](int kt, int buf) {
        const float* Ag = A + (size_t)by * K + kt * 32;
        const float* Bg = B + (size_t)bx * K + kt * 32;
#pragma unroll
        for (int i = 0; i < 4; i++) {
            int e = tid + 256 * i;
            int row = e >> 3, c = (e & 7) * 4;
            cp16(&Abuf[buf][row * SA + c], Ag + (size_t)row * K + c);
            cp16(&Bbuf[buf][row * SA + c], Bg + (size_t)row * K + c);
        }
        cp_commit();
    };

    load_tile(0, 0);
    for (int kt = 0; kt < nkt; kt++) {
        cp_wait<0>();
        __syncthreads();
        if (kt + 1 < nkt) load_tile(kt + 1, (kt + 1) & 1);

        const uint32_t* As = (const uint32_t*)Abuf[kt & 1];
        const uint32_t* Bs = (const uint32_t*)Bbuf[kt & 1];
#pragma unroll
        for (int ks = 0; ks < 4; ks++) {
            uint32_t af[4][4], bf[4][2];
#pragma unroll
            for (int mt = 0; mt < 4; mt++) {
                int r = mW + mt * 16 + g;
                af[mt][0] = As[r * SA + ks * 8 + tig];
                af[mt][1] = As[(r + 8) * SA + ks * 8 + tig];
                af[mt][2] = As[r * SA + ks * 8 + tig + 4];
                af[mt][3] = As[(r + 8) * SA + ks * 8 + tig + 4];
            }
#pragma unroll
            for (int nt = 0; nt < 4; nt++) {
                int r = nW + nt * 8 + g;
                bf[nt][0] = Bs[r * SA + ks * 8 + tig];
                bf[nt][1] = Bs[r * SA + ks * 8 + tig + 4];
            }
#pragma unroll
            for (int mt = 0; mt < 4; mt++)
#pragma unroll
                for (int nt = 0; nt < 4; nt++)
                    mma8(acc[mt][nt], af[mt][0], af[mt][1], af[mt][2], af[mt][3],
                         bf[nt][0], bf[nt][1]);
        }
    }

#pragma unroll
    for (int mt = 0; mt < 4; mt++) {
#pragma unroll
        for (int nt = 0; nt < 4; nt++) {
            int row = by + mW + mt * 16 + g;
            int col = bx + nW + nt * 8 + tig * 2;
            float v0 = acc[mt][nt][0], v1 = acc[mt][nt][1];
            float v2 = acc[mt][nt][2], v3 = acc[mt][nt][3];
            if (ROUND_OUT) {
                v0 = __uint_as_float(f2tf(v0));
                v1 = __uint_as_float(f2tf(v1));
                v2 = __uint_as_float(f2tf(v2));
                v3 = __uint_as_float(f2tf(v3));
            }
            *(float2*)&C[(size_t)row * N + col] = make_float2(v0, v1);
            *(float2*)&C[(size_t)(row + 8) * N + col] = make_float2(v2, v3);
        }
    }
}

// ---------------------------------------------------------------------------
// Attention v2: row-partitioned warps, P stays in registers.
// Block = 128 Q-rows x 1 head; 8 warps, each owns 16 Q-rows and computes its
// full 16x64 S stripe, converts accumulator->A-fragment via quad shuffles,
// then O += P V. One __syncthreads per k-tile; K/V double-buffered cp.async.
// ---------------------------------------------------------------------------
#define AS 68
#define ATT_SMEM ((128 * AS + 4 * 64 * AS) * 4)

__global__ __launch_bounds__(256, 2) void attn_mma(const float* __restrict__ qkv,
                                                   float* __restrict__ outp) {
    extern __shared__ float sm[];
    float* Qs = sm;                                   // 128 x AS
    float* Kb[2] = {Qs + 128 * AS, Qs + 128 * AS + 64 * AS};
    float* Vb[2] = {Qs + 128 * AS + 2 * 64 * AS, Qs + 128 * AS + 3 * 64 * AS};

    const int h = blockIdx.y;
    const int qb = gridDim.x - 1 - blockIdx.x;        // heavy tiles first
    const int q0 = qb * 128;
    const int tid = threadIdx.x;
    const int wid = tid >> 5, lane = tid & 31;
    const int g = lane >> 2, tig = lane & 3;
    const int mrow = wid * 16;                        // this warp's Q-row base
    const int nkb = 2 * qb + 2;

    auto load_kv = [&](int kb, int buf) {
        const int k0 = kb * 64;
#pragma unroll
        for (int i = 0; i < 4; i++) {
            int e = tid + 256 * i;
            int row = e >> 4, c = (e & 15) * 4;
            size_t base = (size_t)(k0 + row) * QKV_N + h * 64 + c;
            cp16(&Kb[buf][row * AS + c], &qkv[base + 1024]);
            cp16(&Vb[buf][row * AS + c], &qkv[base + 2048]);
        }
        cp_commit();
    };

    // Q tile (128 x 64) + KV(0), one commit group
#pragma unroll
    for (int i = 0; i < 8; i++) {
        int e = tid + 256 * i;
        int row = e >> 4, c = (e & 15) * 4;
        cp16(&Qs[row * AS + c], &qkv[(size_t)(q0 + row) * QKV_N + h * 64 + c]);
    }
    load_kv(0, 0);

    float oacc[8][4];
#pragma unroll
    for (int a = 0; a < 8; a++)
#pragma unroll
        for (int c = 0; c < 4; c++) oacc[a][c] = 0.f;
    float lsum[2] = {0.f, 0.f};

    for (int kb = 0; kb < nkb; kb++) {
        cp_wait<0>();
        __syncthreads();                              // data ready + prev-iter reads done
        if (kb + 1 < nkb) load_kv(kb + 1, (kb + 1) & 1);

        const uint32_t* Qu = (const uint32_t*)Qs;
        const uint32_t* Ku = (const uint32_t*)Kb[kb & 1];
        const uint32_t* Vu = (const uint32_t*)Vb[kb & 1];

        // ---- S = Q K^T : warp's 16 rows x full 64 cols ----
        float sacc[8][4];
#pragma unroll
        for (int a = 0; a < 8; a++)
#pragma unroll
            for (int c = 0; c < 4; c++) sacc[a][c] = 0.f;

#pragma unroll
        for (int ks = 0; ks < 8; ks++) {
            uint32_t a0 = Qu[(mrow + g) * AS + ks * 8 + tig];
            uint32_t a1 = Qu[(mrow + g + 8) * AS + ks * 8 + tig];
            uint32_t a2 = Qu[(mrow + g) * AS + ks * 8 + tig + 4];
            uint32_t a3 = Qu[(mrow + g + 8) * AS + ks * 8 + tig + 4];
#pragma unroll
            for (int nt = 0; nt < 8; nt++) {
                int r = nt * 8 + g;
                uint32_t b0 = Ku[r * AS + ks * 8 + tig];
                uint32_t b1 = Ku[r * AS + ks * 8 + tig + 4];
                mma8(sacc[nt], a0, a1, a2, a3, b0, b1);
            }
        }

        // ---- softmax numerator (fixed-max), mask, tf32 round; P in regs ----
        const int k0 = kb * 64;
        const bool diag = (kb >= 2 * qb);             // partially masked tiles
#pragma unroll
        for (int nt = 0; nt < 8; nt++) {
#pragma unroll
            for (int e = 0; e < 4; e++) {
                int row = q0 + mrow + g + ((e >> 1) << 3);
                int col = k0 + nt * 8 + tig * 2 + (e & 1);
                float s = sacc[nt][e] * 0.125f;
                s = fminf(fmaxf(s, -10.f), 10.f);
                float p = __expf(s - 10.f);
                if (diag && col > row) p = 0.f;
                p = __uint_as_float(f2tf(p));
                lsum[e >> 1] += p;
                sacc[nt][e] = p;
            }
        }

        // ---- O += P V : accumulator -> A-fragment via quad shuffles ----
        const int srcA = 4 * g + (tig >> 1);
        const int srcB = srcA + 2;
        const bool odd = (tig & 1);
#pragma unroll
        for (int ks = 0; ks < 8; ks++) {
            float v0 = __shfl_sync(0xffffffffu, sacc[ks][0], srcA);
            float v1 = __shfl_sync(0xffffffffu, sacc[ks][1], srcA);
            float v2 = __shfl_sync(0xffffffffu, sacc[ks][2], srcA);
            float v3 = __shfl_sync(0xffffffffu, sacc[ks][3], srcA);
            float w0 = __shfl_sync(0xffffffffu, sacc[ks][0], srcB);
            float w1 = __shfl_sync(0xffffffffu, sacc[ks][1], srcB);
            float w2 = __shfl_sync(0xffffffffu, sacc[ks][2], srcB);
            float w3 = __shfl_sync(0xffffffffu, sacc[ks][3], srcB);
            uint32_t a0 = __float_as_uint(odd ? v1 : v0);   // (g,     tig)
            uint32_t a1 = __float_as_uint(odd ? v3 : v2);   // (g+8,   tig)
            uint32_t a2 = __float_as_uint(odd ? w1 : w0);   // (g,     tig+4)
            uint32_t a3 = __float_as_uint(odd ? w3 : w2);   // (g+8,   tig+4)
#pragma unroll
            for (int nt = 0; nt < 8; nt++) {
                int col = nt * 8 + g;
                uint32_t b0 = Vu[(ks * 8 + tig) * AS + col];
                uint32_t b1 = Vu[(ks * 8 + tig + 4) * AS + col];
                mma8(oacc[nt], a0, a1, a2, a3, b0, b1);
            }
        }
        // no end barrier: next iteration's barrier covers buffer reuse
    }

    // ---- row-sum reduction inside the quad, then output (rounded tf32) ----
#pragma unroll
    for (int e = 0; e < 2; e++) {
        lsum[e] += __shfl_xor_sync(0xffffffffu, lsum[e], 1);
        lsum[e] += __shfl_xor_sync(0xffffffffu, lsum[e], 2);
    }
    float inv0 = 1.f / lsum[0];
    float inv1 = 1.f / lsum[1];

#pragma unroll
    for (int nt = 0; nt < 8; nt++) {
        int col = h * 64 + nt * 8 + tig * 2;
        int row0 = q0 + mrow + g;
        uint2 u;
        u.x = f2tf(oacc[nt][0] * inv0);
        u.y = f2tf(oacc[nt][1] * inv0);
        *(uint2*)&outp[(size_t)row0 * D_MODEL + col] = u;
        u.x = f2tf(oacc[nt][2] * inv1);
        u.y = f2tf(oacc[nt][3] * inv1);
        *(uint2*)&outp[(size_t)(row0 + 8) * D_MODEL + col] = u;
    }
}

// ---------------------------------------------------------------------------
// Launch
// ---------------------------------------------------------------------------
extern "C" void kernel_launch(void* const* d_in, const int* in_sizes, int n_in,
                              void* d_out, int out_size) {
    const float* x    = (const float*)d_in[0];   // [4096,1024]
    const float* Wqkv = (const float*)d_in[1];   // [3072,1024]
    const float* Wout = (const float*)d_in[2];   // [1024,1024]
    float* out = (float*)d_out;                  // [4096,1024]

    float *qkv, *attn, *xr, *wqkvr, *woutr;
    cudaGetSymbolAddress((void**)&qkv, g_qkv);
    cudaGetSymbolAddress((void**)&attn, g_attn);
    cudaGetSymbolAddress((void**)&xr, g_xr);
    cudaGetSymbolAddress((void**)&wqkvr, g_wqkvr);
    cudaGetSymbolAddress((void**)&woutr, g_woutr);

    cudaFuncSetAttribute(gemm_tf32<true>, cudaFuncAttributeMaxDynamicSharedMemorySize, GEMM_SMEM);
    cudaFuncSetAttribute(gemm_tf32<false>, cudaFuncAttributeMaxDynamicSharedMemorySize, GEMM_SMEM);
    cudaFuncSetAttribute(attn_mma, cudaFuncAttributeMaxDynamicSharedMemorySize, ATT_SMEM);

    // 0) round inputs to tf32 (rna)
    round_k<<<(T_TOK * D_MODEL / 4 + 255) / 256, 256>>>((const float4*)x, (float4*)xr,
                                                        T_TOK * D_MODEL / 4);
    round_k<<<(QKV_N * D_MODEL / 4 + 255) / 256, 256>>>((const float4*)Wqkv, (float4*)wqkvr,
                                                        QKV_N * D_MODEL / 4);
    round_k<<<(D_MODEL * D_MODEL / 4 + 255) / 256, 256>>>((const float4*)Wout, (float4*)woutr,
                                                          D_MODEL * D_MODEL / 4);

    // 1) QKV projection
    gemm_tf32<true><<<dim3(QKV_N / 128, T_TOK / 128), 256, GEMM_SMEM>>>(
        xr, wqkvr, qkv, T_TOK, QKV_N, D_MODEL);

    // 2) causal clamped attention (row-warp tensor core)
    attn_mma<<<dim3(T_TOK / 128, NH), 256, ATT_SMEM>>>(qkv, attn);

    // 3) output projection
    gemm_tf32<false><<<dim3(D_MODEL / 128, T_TOK / 128), 256, GEMM_SMEM>>>(
        attn, woutr, out, T_TOK, D_MODEL, D_MODEL);
}

// round 6
// speedup vs baseline: 2.3267x; 2.3267x over previous
#include <cuda_runtime.h>
#include <cuda_fp16.h>
#include <cstdint>

#define T_TOK 4096
#define D_MODEL 1024
#define NH 16
#define QKV_N 3072

// Scratch (__device__ globals per allocation rules) — all fp16 now
__device__ __half g_qkvh[T_TOK * QKV_N];     // q|k|v
__device__ __half g_attnh[T_TOK * D_MODEL];  // attention out
__device__ __half g_xh[T_TOK * D_MODEL];
__device__ __half g_wqkvh[QKV_N * D_MODEL];
__device__ __half g_wouth[D_MODEL * D_MODEL];

// ---------------------------------------------------------------------------
// helpers
// ---------------------------------------------------------------------------
__device__ __forceinline__ void cp16(void* smem, const void* gmem) {
    uint32_t s = (uint32_t)__cvta_generic_to_shared(smem);
    asm volatile("cp.async.cg.shared.global [%0], [%1], 16;" :: "r"(s), "l"(gmem));
}
__device__ __forceinline__ void cp_commit() { asm volatile("cp.async.commit_group;"); }
template <int N> __device__ __forceinline__ void cp_wait() {
    asm volatile("cp.async.wait_group %0;" :: "n"(N));
}
__device__ __forceinline__ uint32_t pack2(float a, float b) {
    __half2 h = __floats2half2_rn(a, b);   // a -> low (first element)
    return *reinterpret_cast<uint32_t*>(&h);
}
__device__ __forceinline__ void ldsm4(uint32_t* r, uint32_t addr) {
    asm volatile("ldmatrix.sync.aligned.m8n8.x4.shared.b16 {%0,%1,%2,%3}, [%4];"
                 : "=r"(r[0]), "=r"(r[1]), "=r"(r[2]), "=r"(r[3]) : "r"(addr));
}
__device__ __forceinline__ void ldsm4t(uint32_t* r, uint32_t addr) {
    asm volatile("ldmatrix.sync.aligned.m8n8.x4.trans.shared.b16 {%0,%1,%2,%3}, [%4];"
                 : "=r"(r[0]), "=r"(r[1]), "=r"(r[2]), "=r"(r[3]) : "r"(addr));
}
// D += A*B, m16n8k16 fp16 in / fp32 acc (A row-major, B col-major)
__device__ __forceinline__ void mma16(float* c, const uint32_t* a, uint32_t b0, uint32_t b1) {
    asm("mma.sync.aligned.m16n8k16.row.col.f32.f16.f16.f32 "
        "{%0,%1,%2,%3}, {%4,%5,%6,%7}, {%8,%9}, {%0,%1,%2,%3};"
        : "+f"(c[0]), "+f"(c[1]), "+f"(c[2]), "+f"(c[3])
        : "r"(a[0]), "r"(a[1]), "r"(a[2]), "r"(a[3]), "r"(b0), "r"(b1));
}

// ---------------------------------------------------------------------------
// fp32 -> fp16 (rn) conversion
// ---------------------------------------------------------------------------
__global__ void round_h(const float4* __restrict__ in, uint2* __restrict__ out, int n4) {
    int i = blockIdx.x * blockDim.x + threadIdx.x;
    if (i >= n4) return;
    float4 v = in[i];
    out[i] = make_uint2(pack2(v.x, v.y), pack2(v.z, v.w));
}

// ---------------------------------------------------------------------------
// fp16 tensor-core GEMM (NT): C[m,n] = sum_k A[m,k]*B[n,k], fp32 accumulate.
// 128x128x32 tiles, 8 warps (2x4 -> 64x32 warp tile), ldmatrix fragments,
// double-buffered cp.async.
// ---------------------------------------------------------------------------
#define SAH 40   // smem row stride in halves (80B): LDSM conflict-free
#define GEMM_SMEM (4 * 128 * SAH * 2)

template <bool HALF_OUT>
__global__ __launch_bounds__(256, 2) void gemm_h(const __half* __restrict__ A,
                                                 const __half* __restrict__ B,
                                                 void* __restrict__ Cv,
                                                 int M, int N, int K) {
    extern __shared__ __half smh[];
    __half* Ab[2] = {smh, smh + 2 * 128 * SAH};
    __half* Bb[2] = {smh + 128 * SAH, smh + 3 * 128 * SAH};
    const uint32_t sbase = (uint32_t)__cvta_generic_to_shared(smh);

    const int tid = threadIdx.x;
    const int wid = tid >> 5, lane = tid & 31;
    const int g = lane >> 2, tig = lane & 3;
    const int mW = (wid >> 2) * 64, nW = (wid & 3) * 32;
    const int by = blockIdx.y * 128, bx = blockIdx.x * 128;

    // ldmatrix lane-address components
    const int lr8 = (lane & 7) + ((lane >> 3) & 1) * 8;  // A-tile row sel
    const int lc8 = (lane >> 4) * 8;                     // A-tile col sel
    const int bn8 = (lane & 7) + (lane >> 4) * 8;        // B n sel
    const int bk8 = ((lane >> 3) & 1) * 8;               // B k sel

    float acc[4][4][4];
#pragma unroll
    for (int a = 0; a < 4; a++)
#pragma unroll
        for (int b = 0; b < 4; b++)
#pragma unroll
            for (int c = 0; c < 4; c++) acc[a][b][c] = 0.f;

    const int nkt = K / 32;

    auto load_tile = [&](int kt, int buf) {
        const __half* Ag = A + (size_t)by * K + kt * 32;
        const __half* Bg = B + (size_t)bx * K + kt * 32;
#pragma unroll
        for (int i = 0; i < 2; i++) {
            int e = tid + 256 * i;                 // 512 chunks each
            int row = e >> 2, c = (e & 3) * 8;
            cp16(&Ab[buf][row * SAH + c], Ag + (size_t)row * K + c);
            cp16(&Bb[buf][row * SAH + c], Bg + (size_t)row * K + c);
        }
        cp_commit();
    };

    load_tile(0, 0);
    for (int kt = 0; kt < nkt; kt++) {
        cp_wait<0>();
        __syncthreads();
        if (kt + 1 < nkt) load_tile(kt + 1, (kt + 1) & 1);

        const uint32_t aoff = sbase + (uint32_t)((kt & 1) ? 2 * 128 * SAH : 0) * 2;
        const uint32_t boff = sbase + (uint32_t)((kt & 1) ? 3 * 128 * SAH : 128 * SAH) * 2;

#pragma unroll
        for (int ks = 0; ks < 2; ks++) {
            uint32_t af[4][4], bf[2][4];
#pragma unroll
            for (int mt = 0; mt < 4; mt++) {
                int r = mW + mt * 16 + lr8;
                int c = ks * 16 + lc8;
                ldsm4(af[mt], aoff + (r * SAH + c) * 2);
            }
#pragma unroll
            for (int nh = 0; nh < 2; nh++) {
                int r = nW + nh * 16 + bn8;
                int c = ks * 16 + bk8;
                ldsm4(bf[nh], boff + (r * SAH + c) * 2);
            }
#pragma unroll
            for (int mt = 0; mt < 4; mt++)
#pragma unroll
                for (int nt = 0; nt < 4; nt++)
                    mma16(acc[mt][nt], af[mt], bf[nt >> 1][(nt & 1) * 2],
                          bf[nt >> 1][(nt & 1) * 2 + 1]);
        }
    }

#pragma unroll
    for (int mt = 0; mt < 4; mt++) {
#pragma unroll
        for (int nt = 0; nt < 4; nt++) {
            int row = by + mW + mt * 16 + g;
            int col = bx + nW + nt * 8 + tig * 2;
            if (HALF_OUT) {
                __half* C = (__half*)Cv;
                *(uint32_t*)&C[(size_t)row * N + col] = pack2(acc[mt][nt][0], acc[mt][nt][1]);
                *(uint32_t*)&C[(size_t)(row + 8) * N + col] = pack2(acc[mt][nt][2], acc[mt][nt][3]);
            } else {
                float* C = (float*)Cv;
                *(float2*)&C[(size_t)row * N + col] = make_float2(acc[mt][nt][0], acc[mt][nt][1]);
                *(float2*)&C[(size_t)(row + 8) * N + col] = make_float2(acc[mt][nt][2], acc[mt][nt][3]);
            }
        }
    }
}

// ---------------------------------------------------------------------------
// fp16 causal attention. Block = 128 Q-rows x head, 8 warps x 16 rows.
// S = Q K^T (m16n8k16), fixed-max softmax in fp32, P packed in-register
// (C-frag == A-frag layout), O += P V with ldmatrix.trans V fragments.
// One barrier per 64-key tile; K/V double-buffered.
// ---------------------------------------------------------------------------
#define KS 72    // smem row stride in halves (144B): LDSM conflict-free
#define ATT_SMEM ((128 * KS + 4 * 64 * KS) * 2)

__global__ __launch_bounds__(256, 2) void attn_h(const __half* __restrict__ qkv,
                                                 __half* __restrict__ outp) {
    extern __shared__ __half smh[];
    __half* Qs = smh;                                  // 128 x KS
    __half* Kb[2] = {smh + 128 * KS, smh + 128 * KS + 2 * 64 * KS};
    __half* Vb[2] = {smh + 128 * KS + 64 * KS, smh + 128 * KS + 3 * 64 * KS};
    const uint32_t sbase = (uint32_t)__cvta_generic_to_shared(smh);
    const uint32_t qoff = sbase;

    const int h = blockIdx.y;
    const int qb = gridDim.x - 1 - blockIdx.x;         // heavy tiles first
    const int q0 = qb * 128;
    const int tid = threadIdx.x;
    const int wid = tid >> 5, lane = tid & 31;
    const int g = lane >> 2, tig = lane & 3;
    const int mrow = wid * 16;
    const int nkb = 2 * qb + 2;

    const int lr8 = (lane & 7) + ((lane >> 3) & 1) * 8;
    const int lc8 = (lane >> 4) * 8;
    const int bn8 = (lane & 7) + (lane >> 4) * 8;
    const int bk8 = ((lane >> 3) & 1) * 8;

    auto load_kv = [&](int kb, int buf) {
        const int k0 = kb * 64;
#pragma unroll
        for (int i = 0; i < 2; i++) {
            int e = tid + 256 * i;                     // 512 chunks each
            int row = e >> 3, c = (e & 7) * 8;
            size_t base = (size_t)(k0 + row) * QKV_N + h * 64 + c;
            cp16(&Kb[buf][row * KS + c], &qkv[base + 1024]);
            cp16(&Vb[buf][row * KS + c], &qkv[base + 2048]);
        }
        cp_commit();
    };

    // Q (128x64) + KV(0) in one commit group
#pragma unroll
    for (int i = 0; i < 4; i++) {
        int e = tid + 256 * i;
        int row = e >> 3, c = (e & 7) * 8;
        cp16(&Qs[row * KS + c], &qkv[(size_t)(q0 + row) * QKV_N + h * 64 + c]);
    }
    load_kv(0, 0);

    float oacc[8][4];
#pragma unroll
    for (int a = 0; a < 8; a++)
#pragma unroll
        for (int c = 0; c < 4; c++) oacc[a][c] = 0.f;
    float lsum[2] = {0.f, 0.f};

    for (int kb = 0; kb < nkb; kb++) {
        cp_wait<0>();
        __syncthreads();
        if (kb + 1 < nkb) load_kv(kb + 1, (kb + 1) & 1);

        const uint32_t koff = sbase + (uint32_t)(128 * KS + (kb & 1) * 2 * 64 * KS) * 2;
        const uint32_t voff = koff + (uint32_t)(64 * KS) * 2;

        // ---- S = Q K^T : 16 rows x 64 keys per warp ----
        float sacc[8][4];
#pragma unroll
        for (int a = 0; a < 8; a++)
#pragma unroll
            for (int c = 0; c < 4; c++) sacc[a][c] = 0.f;

#pragma unroll
        for (int ks = 0; ks < 4; ks++) {               // d-steps of 16
            uint32_t aq[4];
            ldsm4(aq, qoff + ((mrow + lr8) * KS + ks * 16 + lc8) * 2);
#pragma unroll
            for (int nh = 0; nh < 4; nh++) {           // 16 keys per ldsm4
                uint32_t bf[4];
                ldsm4(bf, koff + ((nh * 16 + bn8) * KS + ks * 16 + bk8) * 2);
                mma16(sacc[nh * 2 + 0], aq, bf[0], bf[1]);
                mma16(sacc[nh * 2 + 1], aq, bf[2], bf[3]);
            }
        }

        // ---- softmax numerator (fixed-max), mask; P stays in registers ----
        const int k0 = kb * 64;
        const bool diag = (kb >= 2 * qb);
#pragma unroll
        for (int nt = 0; nt < 8; nt++) {
#pragma unroll
            for (int e = 0; e < 4; e++) {
                int row = q0 + mrow + g + ((e >> 1) << 3);
                int col = k0 + nt * 8 + 2 * tig + (e & 1);
                float s = sacc[nt][e] * 0.125f;
                s = fminf(fmaxf(s, -10.f), 10.f);
                float p = __expf(s - 10.f);
                if (diag && col > row) p = 0.f;
                lsum[e >> 1] += p;
                sacc[nt][e] = p;
            }
        }

        // ---- O += P V : C-frag == A-frag layout, zero shuffles ----
#pragma unroll
        for (int ksp = 0; ksp < 4; ksp++) {            // key-steps of 16
            uint32_t ap[4];
            ap[0] = pack2(sacc[2 * ksp][0], sacc[2 * ksp][1]);
            ap[1] = pack2(sacc[2 * ksp][2], sacc[2 * ksp][3]);
            ap[2] = pack2(sacc[2 * ksp + 1][0], sacc[2 * ksp + 1][1]);
            ap[3] = pack2(sacc[2 * ksp + 1][2], sacc[2 * ksp + 1][3]);
#pragma unroll
            for (int dh = 0; dh < 4; dh++) {           // 16 d-cols per ldsm4t
                uint32_t bf[4];
                ldsm4t(bf, voff + ((ksp * 16 + lr8) * KS + dh * 16 + lc8) * 2);
                mma16(oacc[dh * 2 + 0], ap, bf[0], bf[1]);
                mma16(oacc[dh * 2 + 1], ap, bf[2], bf[3]);
            }
        }
    }

    // ---- quad row-sum reduction, normalize, fp16 store ----
#pragma unroll
    for (int e = 0; e < 2; e++) {
        lsum[e] += __shfl_xor_sync(0xffffffffu, lsum[e], 1);
        lsum[e] += __shfl_xor_sync(0xffffffffu, lsum[e], 2);
    }
    float inv0 = 1.f / lsum[0];
    float inv1 = 1.f / lsum[1];

#pragma unroll
    for (int nt = 0; nt < 8; nt++) {
        int col = h * 64 + nt * 8 + 2 * tig;
        int row0 = q0 + mrow + g;
        *(uint32_t*)&outp[(size_t)row0 * D_MODEL + col] =
            pack2(oacc[nt][0] * inv0, oacc[nt][1] * inv0);
        *(uint32_t*)&outp[(size_t)(row0 + 8) * D_MODEL + col] =
            pack2(oacc[nt][2] * inv1, oacc[nt][3] * inv1);
    }
}

// ---------------------------------------------------------------------------
// Launch
// ---------------------------------------------------------------------------
extern "C" void kernel_launch(void* const* d_in, const int* in_sizes, int n_in,
                              void* d_out, int out_size) {
    const float* x    = (const float*)d_in[0];   // [4096,1024]
    const float* Wqkv = (const float*)d_in[1];   // [3072,1024]
    const float* Wout = (const float*)d_in[2];   // [1024,1024]
    float* out = (float*)d_out;                  // [4096,1024]

    __half *qkvh, *attnh, *xh, *wqkvh, *wouth;
    cudaGetSymbolAddress((void**)&qkvh, g_qkvh);
    cudaGetSymbolAddress((void**)&attnh, g_attnh);
    cudaGetSymbolAddress((void**)&xh, g_xh);
    cudaGetSymbolAddress((void**)&wqkvh, g_wqkvh);
    cudaGetSymbolAddress((void**)&wouth, g_wouth);

    cudaFuncSetAttribute(gemm_h<true>, cudaFuncAttributeMaxDynamicSharedMemorySize, GEMM_SMEM);
    cudaFuncSetAttribute(gemm_h<false>, cudaFuncAttributeMaxDynamicSharedMemorySize, GEMM_SMEM);
    cudaFuncSetAttribute(attn_h, cudaFuncAttributeMaxDynamicSharedMemorySize, ATT_SMEM);

    // 0) inputs -> fp16 (rn)
    round_h<<<(T_TOK * D_MODEL / 4 + 255) / 256, 256>>>((const float4*)x, (uint2*)xh,
                                                        T_TOK * D_MODEL / 4);
    round_h<<<(QKV_N * D_MODEL / 4 + 255) / 256, 256>>>((const float4*)Wqkv, (uint2*)wqkvh,
                                                        QKV_N * D_MODEL / 4);
    round_h<<<(D_MODEL * D_MODEL / 4 + 255) / 256, 256>>>((const float4*)Wout, (uint2*)wouth,
                                                          D_MODEL * D_MODEL / 4);

    // 1) QKV projection (fp16 out feeds attention)
    gemm_h<true><<<dim3(QKV_N / 128, T_TOK / 128), 256, GEMM_SMEM>>>(
        xh, wqkvh, qkvh, T_TOK, QKV_N, D_MODEL);

    // 2) causal clamped attention
    attn_h<<<dim3(T_TOK / 128, NH), 256, ATT_SMEM>>>(qkvh, attnh);

    // 3) output projection (fp32 out)
    gemm_h<false><<<dim3(D_MODEL / 128, T_TOK / 128), 256, GEMM_SMEM>>>(
        attnh, wouth, out, T_TOK, D_MODEL, D_MODEL);
}

// round 8
// speedup vs baseline: 2.3366x; 1.0043x over previous
#include <cuda_runtime.h>
#include <cuda_fp16.h>
#include <cstdint>

#define T_TOK 4096
#define D_MODEL 1024
#define NH 16
#define QKV_N 3072

// Scratch (__device__ globals per allocation rules)
__device__ __half g_qkvh[T_TOK * QKV_N];     // q|k|v
__device__ __half g_attnh[T_TOK * D_MODEL];  // attention out
__device__ __half g_xh[T_TOK * D_MODEL];
__device__ __half g_wqkvh[QKV_N * D_MODEL];
__device__ __half g_wouth[D_MODEL * D_MODEL];

// ---------------------------------------------------------------------------
// helpers
// ---------------------------------------------------------------------------
__device__ __forceinline__ void cp16(void* smem, const void* gmem) {
    uint32_t s = (uint32_t)__cvta_generic_to_shared(smem);
    asm volatile("cp.async.cg.shared.global [%0], [%1], 16;" :: "r"(s), "l"(gmem));
}
__device__ __forceinline__ void cp_commit() { asm volatile("cp.async.commit_group;"); }
template <int N> __device__ __forceinline__ void cp_wait() {
    asm volatile("cp.async.wait_group %0;" :: "n"(N));
}
__device__ __forceinline__ uint32_t pack2(float a, float b) {
    __half2 h = __floats2half2_rn(a, b);
    return *reinterpret_cast<uint32_t*>(&h);
}
__device__ __forceinline__ void ldsm4(uint32_t* r, uint32_t addr) {
    asm volatile("ldmatrix.sync.aligned.m8n8.x4.shared.b16 {%0,%1,%2,%3}, [%4];"
                 : "=r"(r[0]), "=r"(r[1]), "=r"(r[2]), "=r"(r[3]) : "r"(addr));
}
__device__ __forceinline__ void ldsm4t(uint32_t* r, uint32_t addr) {
    asm volatile("ldmatrix.sync.aligned.m8n8.x4.trans.shared.b16 {%0,%1,%2,%3}, [%4];"
                 : "=r"(r[0]), "=r"(r[1]), "=r"(r[2]), "=r"(r[3]) : "r"(addr));
}
__device__ __forceinline__ void mma16(float* c, const uint32_t* a, uint32_t b0, uint32_t b1) {
    asm("mma.sync.aligned.m16n8k16.row.col.f32.f16.f16.f32 "
        "{%0,%1,%2,%3}, {%4,%5,%6,%7}, {%8,%9}, {%0,%1,%2,%3};"
        : "+f"(c[0]), "+f"(c[1]), "+f"(c[2]), "+f"(c[3])
        : "r"(a[0]), "r"(a[1]), "r"(a[2]), "r"(a[3]), "r"(b0), "r"(b1));
}

// ---------------------------------------------------------------------------
// fp32 -> fp16 (rn) conversion
// ---------------------------------------------------------------------------
__global__ void round_h(const float4* __restrict__ in, uint2* __restrict__ out, int n4) {
    int i = blockIdx.x * blockDim.x + threadIdx.x;
    if (i >= n4) return;
    float4 v = in[i];
    out[i] = make_uint2(pack2(v.x, v.y), pack2(v.z, v.w));
}

// ---------------------------------------------------------------------------
// fp16 tensor-core GEMM (NT): unchanged from round 6 (proven 112us QKV).
// ---------------------------------------------------------------------------
#define SAH 40
#define GEMM_SMEM (4 * 128 * SAH * 2)

template <bool HALF_OUT>
__global__ __launch_bounds__(256, 2) void gemm_h(const __half* __restrict__ A,
                                                 const __half* __restrict__ B,
                                                 void* __restrict__ Cv,
                                                 int M, int N, int K) {
    extern __shared__ __half smh[];
    __half* Ab[2] = {smh, smh + 2 * 128 * SAH};
    __half* Bb[2] = {smh + 128 * SAH, smh + 3 * 128 * SAH};
    const uint32_t sbase = (uint32_t)__cvta_generic_to_shared(smh);

    const int tid = threadIdx.x;
    const int wid = tid >> 5, lane = tid & 31;
    const int g = lane >> 2, tig = lane & 3;
    const int mW = (wid >> 2) * 64, nW = (wid & 3) * 32;
    const int by = blockIdx.y * 128, bx = blockIdx.x * 128;

    const int lr8 = (lane & 7) + ((lane >> 3) & 1) * 8;
    const int lc8 = (lane >> 4) * 8;
    const int bn8 = (lane & 7) + (lane >> 4) * 8;
    const int bk8 = ((lane >> 3) & 1) * 8;

    float acc[4][4][4];
#pragma unroll
    for (int a = 0; a < 4; a++)
#pragma unroll
        for (int b = 0; b < 4; b++)
#pragma unroll
            for (int c = 0; c < 4; c++) acc[a][b][c] = 0.f;

    const int nkt = K / 32;

    auto load_tile = [&](int kt, int buf) {
        const __half* Ag = A + (size_t)by * K + kt * 32;
        const __half* Bg = B + (size_t)bx * K + kt * 32;
#pragma unroll
        for (int i = 0; i < 2; i++) {
            int e = tid + 256 * i;
            int row = e >> 2, c = (e & 3) * 8;
            cp16(&Ab[buf][row * SAH + c], Ag + (size_t)row * K + c);
            cp16(&Bb[buf][row * SAH + c], Bg + (size_t)row * K + c);
        }
        cp_commit();
    };

    load_tile(0, 0);
    for (int kt = 0; kt < nkt; kt++) {
        cp_wait<0>();
        __syncthreads();
        if (kt + 1 < nkt) load_tile(kt + 1, (kt + 1) & 1);

        const uint32_t aoff = sbase + (uint32_t)((kt & 1) ? 2 * 128 * SAH : 0) * 2;
        const uint32_t boff = sbase + (uint32_t)((kt & 1) ? 3 * 128 * SAH : 128 * SAH) * 2;

#pragma unroll
        for (int ks = 0; ks < 2; ks++) {
            uint32_t af[4][4], bf[2][4];
#pragma unroll
            for (int mt = 0; mt < 4; mt++) {
                int r = mW + mt * 16 + lr8;
                int c = ks * 16 + lc8;
                ldsm4(af[mt], aoff + (r * SAH + c) * 2);
            }
#pragma unroll
            for (int nh = 0; nh < 2; nh++) {
                int r = nW + nh * 16 + bn8;
                int c = ks * 16 + bk8;
                ldsm4(bf[nh], boff + (r * SAH + c) * 2);
            }
#pragma unroll
            for (int mt = 0; mt < 4; mt++)
#pragma unroll
                for (int nt = 0; nt < 4; nt++)
                    mma16(acc[mt][nt], af[mt], bf[nt >> 1][(nt & 1) * 2],
                          bf[nt >> 1][(nt & 1) * 2 + 1]);
        }
    }

#pragma unroll
    for (int mt = 0; mt < 4; mt++) {
#pragma unroll
        for (int nt = 0; nt < 4; nt++) {
            int row = by + mW + mt * 16 + g;
            int col = bx + nW + nt * 8 + tig * 2;
            if (HALF_OUT) {
                __half* C = (__half*)Cv;
                *(uint32_t*)&C[(size_t)row * N + col] = pack2(acc[mt][nt][0], acc[mt][nt][1]);
                *(uint32_t*)&C[(size_t)(row + 8) * N + col] = pack2(acc[mt][nt][2], acc[mt][nt][3]);
            } else {
                float* C = (float*)Cv;
                *(float2*)&C[(size_t)row * N + col] = make_float2(acc[mt][nt][0], acc[mt][nt][1]);
                *(float2*)&C[(size_t)(row + 8) * N + col] = make_float2(acc[mt][nt][2], acc[mt][nt][3]);
            }
        }
    }
}

// ---------------------------------------------------------------------------
// fp16 causal attention v3: 4 warps x 32 Q-rows (denser mma per ldsm).
// Block = 128 Q-rows x head, 128 threads. Two independent 16-row mma chains
// per warp; P stays in registers (C-frag == A-frag). K/V double-buffered.
// ---------------------------------------------------------------------------
#define KS 72
#define ATT_SMEM ((128 * KS + 4 * 64 * KS) * 2)

__global__ __launch_bounds__(128, 3) void attn_h(const __half* __restrict__ qkv,
                                                 __half* __restrict__ outp) {
    extern __shared__ __half smh[];
    __half* Qs = smh;
    __half* Kb[2] = {smh + 128 * KS, smh + 128 * KS + 2 * 64 * KS};
    __half* Vb[2] = {smh + 128 * KS + 64 * KS, smh + 128 * KS + 3 * 64 * KS};
    const uint32_t sbase = (uint32_t)__cvta_generic_to_shared(smh);
    const uint32_t qoff = sbase;

    const int h = blockIdx.y;
    const int qb = gridDim.x - 1 - blockIdx.x;         // heavy tiles first
    const int q0 = qb * 128;
    const int tid = threadIdx.x;
    const int wid = tid >> 5, lane = tid & 31;
    const int g = lane >> 2, tig = lane & 3;
    const int mrow = wid * 32;                         // warp owns 32 Q-rows
    const int nkb = 2 * qb + 2;

    const int lr8 = (lane & 7) + ((lane >> 3) & 1) * 8;
    const int lc8 = (lane >> 4) * 8;
    const int bn8 = (lane & 7) + (lane >> 4) * 8;
    const int bk8 = ((lane >> 3) & 1) * 8;

    auto load_kv = [&](int kb, int buf) {
        const int k0 = kb * 64;
#pragma unroll
        for (int i = 0; i < 4; i++) {
            int e = tid + 128 * i;                     // 512 chunks each
            int row = e >> 3, c = (e & 7) * 8;
            size_t base = (size_t)(k0 + row) * QKV_N + h * 64 + c;
            cp16(&Kb[buf][row * KS + c], &qkv[base + 1024]);
            cp16(&Vb[buf][row * KS + c], &qkv[base + 2048]);
        }
        cp_commit();
    };

    // Q (128x64) + KV(0) in one commit group
#pragma unroll
    for (int i = 0; i < 8; i++) {
        int e = tid + 128 * i;
        int row = e >> 3, c = (e & 7) * 8;
        cp16(&Qs[row * KS + c], &qkv[(size_t)(q0 + row) * QKV_N + h * 64 + c]);
    }
    load_kv(0, 0);

    float oacc[2][8][4];
#pragma unroll
    for (int hh = 0; hh < 2; hh++)
#pragma unroll
        for (int a = 0; a < 8; a++)
#pragma unroll
            for (int c = 0; c < 4; c++) oacc[hh][a][c] = 0.f;
    float lsum[2][2] = {{0.f, 0.f}, {0.f, 0.f}};

    for (int kb = 0; kb < nkb; kb++) {
        cp_wait<0>();
        __syncthreads();
        if (kb + 1 < nkb) load_kv(kb + 1, (kb + 1) & 1);

        const uint32_t koff = sbase + (uint32_t)(128 * KS + (kb & 1) * 2 * 64 * KS) * 2;
        const uint32_t voff = koff + (uint32_t)(64 * KS) * 2;

        // ---- S = Q K^T : 32 rows x 64 keys per warp ----
        float sacc[2][8][4];
#pragma unroll
        for (int hh = 0; hh < 2; hh++)
#pragma unroll
            for (int a = 0; a < 8; a++)
#pragma unroll
                for (int c = 0; c < 4; c++) sacc[hh][a][c] = 0.f;

#pragma unroll
        for (int ks = 0; ks < 4; ks++) {               // d-steps of 16
            uint32_t aq[2][4];
            ldsm4(aq[0], qoff + ((mrow + lr8) * KS + ks * 16 + lc8) * 2);
            ldsm4(aq[1], qoff + ((mrow + 16 + lr8) * KS + ks * 16 + lc8) * 2);
#pragma unroll
            for (int nh = 0; nh < 4; nh++) {           // 16 keys per ldsm4
                uint32_t bf[4];
                ldsm4(bf, koff + ((nh * 16 + bn8) * KS + ks * 16 + bk8) * 2);
#pragma unroll
                for (int hh = 0; hh < 2; hh++) {
                    mma16(sacc[hh][nh * 2 + 0], aq[hh], bf[0], bf[1]);
                    mma16(sacc[hh][nh * 2 + 1], aq[hh], bf[2], bf[3]);
                }
            }
        }

        // ---- softmax numerator (fixed-max), mask; P stays in registers ----
        const int k0 = kb * 64;
        const bool diag = (kb >= 2 * qb);
#pragma unroll
        for (int hh = 0; hh < 2; hh++) {
#pragma unroll
            for (int nt = 0; nt < 8; nt++) {
#pragma unroll
                for (int e = 0; e < 4; e++) {
                    int row = q0 + mrow + hh * 16 + g + ((e >> 1) << 3);
                    int col = k0 + nt * 8 + 2 * tig + (e & 1);
                    float s = sacc[hh][nt][e] * 0.125f;
                    s = fminf(fmaxf(s, -10.f), 10.f);
                    float p = __expf(s - 10.f);
                    if (diag && col > row) p = 0.f;
                    lsum[hh][e >> 1] += p;
                    sacc[hh][nt][e] = p;
                }
            }
        }

        // ---- O += P V : C-frag == A-frag, V fragments shared across halves ----
#pragma unroll
        for (int ksp = 0; ksp < 4; ksp++) {            // key-steps of 16
            uint32_t ap[2][4];
#pragma unroll
            for (int hh = 0; hh < 2; hh++) {
                ap[hh][0] = pack2(sacc[hh][2 * ksp][0], sacc[hh][2 * ksp][1]);
                ap[hh][1] = pack2(sacc[hh][2 * ksp][2], sacc[hh][2 * ksp][3]);
                ap[hh][2] = pack2(sacc[hh][2 * ksp + 1][0], sacc[hh][2 * ksp + 1][1]);
                ap[hh][3] = pack2(sacc[hh][2 * ksp + 1][2], sacc[hh][2 * ksp + 1][3]);
            }
#pragma unroll
            for (int dh = 0; dh < 4; dh++) {           // 16 d-cols per ldsm4t
                uint32_t bf[4];
                ldsm4t(bf, voff + ((ksp * 16 + lr8) * KS + dh * 16 + lc8) * 2);
#pragma unroll
                for (int hh = 0; hh < 2; hh++) {
                    mma16(oacc[hh][dh * 2 + 0], ap[hh], bf[0], bf[1]);
                    mma16(oacc[hh][dh * 2 + 1], ap[hh], bf[2], bf[3]);
                }
            }
        }
    }

    // ---- quad row-sum reduction, normalize, fp16 store ----
#pragma unroll
    for (int hh = 0; hh < 2; hh++)
#pragma unroll
        for (int e = 0; e < 2; e++) {
            lsum[hh][e] += __shfl_xor_sync(0xffffffffu, lsum[hh][e], 1);
            lsum[hh][e] += __shfl_xor_sync(0xffffffffu, lsum[hh][e], 2);
        }

#pragma unroll
    for (int hh = 0; hh < 2; hh++) {
        float inv0 = 1.f / lsum[hh][0];
        float inv1 = 1.f / lsum[hh][1];
#pragma unroll
        for (int nt = 0; nt < 8; nt++) {
            int col = h * 64 + nt * 8 + 2 * tig;
            int row0 = q0 + mrow + hh * 16 + g;
            *(uint32_t*)&outp[(size_t)row0 * D_MODEL + col] =
                pack2(oacc[hh][nt][0] * inv0, oacc[hh][nt][1] * inv0);
            *(uint32_t*)&outp[(size_t)(row0 + 8) * D_MODEL + col] =
                pack2(oacc[hh][nt][2] * inv1, oacc[hh][nt][3] * inv1);
        }
    }
}

// ---------------------------------------------------------------------------
// Launch
// ---------------------------------------------------------------------------
extern "C" void kernel_launch(void* const* d_in, const int* in_sizes, int n_in,
                              void* d_out, int out_size) {
    const float* x    = (const float*)d_in[0];   // [4096,1024]
    const float* Wqkv = (const float*)d_in[1];   // [3072,1024]
    const float* Wout = (const float*)d_in[2];   // [1024,1024]
    float* out = (float*)d_out;                  // [4096,1024]

    __half *qkvh, *attnh, *xh, *wqkvh, *wouth;
    cudaGetSymbolAddress((void**)&qkvh, g_qkvh);
    cudaGetSymbolAddress((void**)&attnh, g_attnh);
    cudaGetSymbolAddress((void**)&xh, g_xh);
    cudaGetSymbolAddress((void**)&wqkvh, g_wqkvh);
    cudaGetSymbolAddress((void**)&wouth, g_wouth);

    cudaFuncSetAttribute(gemm_h<true>, cudaFuncAttributeMaxDynamicSharedMemorySize, GEMM_SMEM);
    cudaFuncSetAttribute(gemm_h<false>, cudaFuncAttributeMaxDynamicSharedMemorySize, GEMM_SMEM);
    cudaFuncSetAttribute(attn_h, cudaFuncAttributeMaxDynamicSharedMemorySize, ATT_SMEM);

    // 0) inputs -> fp16 (rn)
    round_h<<<(T_TOK * D_MODEL / 4 + 255) / 256, 256>>>((const float4*)x, (uint2*)xh,
                                                        T_TOK * D_MODEL / 4);
    round_h<<<(QKV_N * D_MODEL / 4 + 255) / 256, 256>>>((const float4*)Wqkv, (uint2*)wqkvh,
                                                        QKV_N * D_MODEL / 4);
    round_h<<<(D_MODEL * D_MODEL / 4 + 255) / 256, 256>>>((const float4*)Wout, (uint2*)wouth,
                                                          D_MODEL * D_MODEL / 4);

    // 1) QKV projection
    gemm_h<true><<<dim3(QKV_N / 128, T_TOK / 128), 256, GEMM_SMEM>>>(
        xh, wqkvh, qkvh, T_TOK, QKV_N, D_MODEL);

    // 2) causal clamped attention (4-warp, 32 rows/warp)
    attn_h<<<dim3(T_TOK / 128, NH), 128, ATT_SMEM>>>(qkvh, attnh);

    // 3) output projection (fp32 out)
    gemm_h<false><<<dim3(D_MODEL / 128, T_TOK / 128), 256, GEMM_SMEM>>>(
        attnh, wouth, out, T_TOK, D_MODEL, D_MODEL);
}

// round 9
// speedup vs baseline: 2.4380x; 1.0434x over previous
#include <cuda_runtime.h>
#include <cuda_fp16.h>
#include <cstdint>

#define T_TOK 4096
#define D_MODEL 1024
#define NH 16
#define QKV_N 3072

// Scratch (__device__ globals per allocation rules)
__device__ __half g_qkvh[T_TOK * QKV_N];     // q(prescaled)|k|v
__device__ __half g_attnh[T_TOK * D_MODEL];  // attention out
__device__ __half g_xh[T_TOK * D_MODEL];
__device__ __half g_wqkvh[QKV_N * D_MODEL];
__device__ __half g_wouth[D_MODEL * D_MODEL];

// ---------------------------------------------------------------------------
// helpers
// ---------------------------------------------------------------------------
__device__ __forceinline__ void cp16(void* smem, const void* gmem) {
    uint32_t s = (uint32_t)__cvta_generic_to_shared(smem);
    asm volatile("cp.async.cg.shared.global [%0], [%1], 16;" :: "r"(s), "l"(gmem));
}
__device__ __forceinline__ void cp_commit() { asm volatile("cp.async.commit_group;"); }
template <int N> __device__ __forceinline__ void cp_wait() {
    asm volatile("cp.async.wait_group %0;" :: "n"(N));
}
__device__ __forceinline__ uint32_t pack2(float a, float b) {
    __half2 h = __floats2half2_rn(a, b);
    return *reinterpret_cast<uint32_t*>(&h);
}
__device__ __forceinline__ float ex2(float x) {
    float r; asm("ex2.approx.ftz.f32 %0, %1;" : "=f"(r) : "f"(x)); return r;
}
__device__ __forceinline__ void ldsm4(uint32_t* r, uint32_t addr) {
    asm volatile("ldmatrix.sync.aligned.m8n8.x4.shared.b16 {%0,%1,%2,%3}, [%4];"
                 : "=r"(r[0]), "=r"(r[1]), "=r"(r[2]), "=r"(r[3]) : "r"(addr));
}
__device__ __forceinline__ void ldsm4t(uint32_t* r, uint32_t addr) {
    asm volatile("ldmatrix.sync.aligned.m8n8.x4.trans.shared.b16 {%0,%1,%2,%3}, [%4];"
                 : "=r"(r[0]), "=r"(r[1]), "=r"(r[2]), "=r"(r[3]) : "r"(addr));
}
__device__ __forceinline__ void mma16(float* c, const uint32_t* a, uint32_t b0, uint32_t b1) {
    asm("mma.sync.aligned.m16n8k16.row.col.f32.f16.f16.f32 "
        "{%0,%1,%2,%3}, {%4,%5,%6,%7}, {%8,%9}, {%0,%1,%2,%3};"
        : "+f"(c[0]), "+f"(c[1]), "+f"(c[2]), "+f"(c[3])
        : "r"(a[0]), "r"(a[1]), "r"(a[2]), "r"(a[3]), "r"(b0), "r"(b1));
}

// ---------------------------------------------------------------------------
// fused fp32 -> fp16 rounding for all three inputs (one launch)
// ---------------------------------------------------------------------------
__global__ void round_all(const float4* __restrict__ a, uint2* __restrict__ ao, int na,
                          const float4* __restrict__ b, uint2* __restrict__ bo, int nb,
                          const float4* __restrict__ c, uint2* __restrict__ co, int nc) {
    int i = blockIdx.x * blockDim.x + threadIdx.x;
    const float4* src;
    uint2* dst;
    if (i < na) { src = a + i; dst = ao + i; }
    else if (i < na + nb) { src = b + (i - na); dst = bo + (i - na); }
    else if (i < na + nb + nc) { src = c + (i - na - nb); dst = co + (i - na - nb); }
    else return;
    float4 v = *src;
    *dst = make_uint2(pack2(v.x, v.y), pack2(v.z, v.w));
}

// ---------------------------------------------------------------------------
// fp16 tensor-core GEMM (NT), 3-stage cp.async pipeline.
// C[m,n] = sum_k A[m,k]*B[n,k], fp32 accumulate. 128x128x32 tiles, 8 warps.
// HALF_OUT: fp16 store, with columns < 1024 (the Q block) pre-scaled by 0.125.
// ---------------------------------------------------------------------------
#define SAH 40
#define STG (2 * 128 * SAH)              // halves per stage (A then B)
#define GEMM_SMEM (3 * STG * 2)          // 61440 B

template <bool HALF_OUT>
__global__ __launch_bounds__(256, 2) void gemm_h(const __half* __restrict__ A,
                                                 const __half* __restrict__ B,
                                                 void* __restrict__ Cv,
                                                 int M, int N, int K) {
    extern __shared__ __half smh[];
    const uint32_t sbase = (uint32_t)__cvta_generic_to_shared(smh);

    const int tid = threadIdx.x;
    const int wid = tid >> 5, lane = tid & 31;
    const int g = lane >> 2, tig = lane & 3;
    const int mW = (wid >> 2) * 64, nW = (wid & 3) * 32;
    const int by = blockIdx.y * 128, bx = blockIdx.x * 128;

    const int lr8 = (lane & 7) + ((lane >> 3) & 1) * 8;
    const int lc8 = (lane >> 4) * 8;
    const int bn8 = (lane & 7) + (lane >> 4) * 8;
    const int bk8 = ((lane >> 3) & 1) * 8;

    float acc[4][4][4];
#pragma unroll
    for (int a = 0; a < 4; a++)
#pragma unroll
        for (int b = 0; b < 4; b++)
#pragma unroll
            for (int c = 0; c < 4; c++) acc[a][b][c] = 0.f;

    const int nkt = K / 32;

    auto fill = [&](int kt, int s) {
        const __half* Ag = A + (size_t)by * K + kt * 32;
        const __half* Bg = B + (size_t)bx * K + kt * 32;
        __half* Ab = smh + s * STG;
        __half* Bb = Ab + 128 * SAH;
#pragma unroll
        for (int i = 0; i < 2; i++) {
            int e = tid + 256 * i;
            int row = e >> 2, c = (e & 3) * 8;
            cp16(&Ab[row * SAH + c], Ag + (size_t)row * K + c);
            cp16(&Bb[row * SAH + c], Bg + (size_t)row * K + c);
        }
        cp_commit();
    };

    fill(0, 0);
    fill(1, 1);
    for (int kt = 0; kt < nkt; kt++) {
        const int s = kt % 3;
        if (kt < nkt - 1) cp_wait<1>(); else cp_wait<0>();
        __syncthreads();
        if (kt + 2 < nkt) fill(kt + 2, (kt + 2) % 3);

        const uint32_t aoff = sbase + (uint32_t)(s * STG) * 2;
        const uint32_t boff = aoff + (uint32_t)(128 * SAH) * 2;

#pragma unroll
        for (int ks = 0; ks < 2; ks++) {
            uint32_t af[4][4], bf[2][4];
#pragma unroll
            for (int mt = 0; mt < 4; mt++) {
                int r = mW + mt * 16 + lr8;
                int c = ks * 16 + lc8;
                ldsm4(af[mt], aoff + (r * SAH + c) * 2);
            }
#pragma unroll
            for (int nh = 0; nh < 2; nh++) {
                int r = nW + nh * 16 + bn8;
                int c = ks * 16 + bk8;
                ldsm4(bf[nh], boff + (r * SAH + c) * 2);
            }
#pragma unroll
            for (int mt = 0; mt < 4; mt++)
#pragma unroll
                for (int nt = 0; nt < 4; nt++)
                    mma16(acc[mt][nt], af[mt], bf[nt >> 1][(nt & 1) * 2],
                          bf[nt >> 1][(nt & 1) * 2 + 1]);
        }
    }

    // epilogue; for HALF_OUT (QKV) pre-scale the Q block (cols < 1024) by 1/8
    const float sc = (HALF_OUT && bx < 1024) ? 0.125f : 1.f;
#pragma unroll
    for (int mt = 0; mt < 4; mt++) {
#pragma unroll
        for (int nt = 0; nt < 4; nt++) {
            int row = by + mW + mt * 16 + g;
            int col = bx + nW + nt * 8 + tig * 2;
            if (HALF_OUT) {
                __half* C = (__half*)Cv;
                *(uint32_t*)&C[(size_t)row * N + col] =
                    pack2(acc[mt][nt][0] * sc, acc[mt][nt][1] * sc);
                *(uint32_t*)&C[(size_t)(row + 8) * N + col] =
                    pack2(acc[mt][nt][2] * sc, acc[mt][nt][3] * sc);
            } else {
                float* C = (float*)Cv;
                *(float2*)&C[(size_t)row * N + col] = make_float2(acc[mt][nt][0], acc[mt][nt][1]);
                *(float2*)&C[(size_t)(row + 8) * N + col] = make_float2(acc[mt][nt][2], acc[mt][nt][3]);
            }
        }
    }
}

// ---------------------------------------------------------------------------
// fp16 causal attention: 4 warps x 32 Q-rows, 3-stage K/V pipeline.
// Q pre-scaled by 1/8; p = ex2(fma(s, log2e, -10*log2e)) with clamp.
// ---------------------------------------------------------------------------
#define KS 72
#define KVSTG (2 * 64 * KS)              // halves per K/V stage
#define ATT_SMEM ((128 * KS + 3 * KVSTG) * 2)   // 73728 B

__global__ __launch_bounds__(128, 3) void attn_h(const __half* __restrict__ qkv,
                                                 __half* __restrict__ outp) {
    extern __shared__ __half smh[];
    __half* Qs = smh;
    const uint32_t sbase = (uint32_t)__cvta_generic_to_shared(smh);
    const uint32_t qoff = sbase;

    const int h = blockIdx.y;
    const int qb = gridDim.x - 1 - blockIdx.x;         // heavy tiles first
    const int q0 = qb * 128;
    const int tid = threadIdx.x;
    const int wid = tid >> 5, lane = tid & 31;
    const int g = lane >> 2, tig = lane & 3;
    const int mrow = wid * 32;
    const int nkb = 2 * qb + 2;

    const int lr8 = (lane & 7) + ((lane >> 3) & 1) * 8;
    const int lc8 = (lane >> 4) * 8;
    const int bn8 = (lane & 7) + (lane >> 4) * 8;
    const int bk8 = ((lane >> 3) & 1) * 8;

    auto load_kv = [&](int kb, int s) {
        const int k0 = kb * 64;
        __half* Kb = smh + 128 * KS + s * KVSTG;
        __half* Vb = Kb + 64 * KS;
#pragma unroll
        for (int i = 0; i < 4; i++) {
            int e = tid + 128 * i;
            int row = e >> 3, c = (e & 7) * 8;
            size_t base = (size_t)(k0 + row) * QKV_N + h * 64 + c;
            cp16(&Kb[row * KS + c], &qkv[base + 1024]);
            cp16(&Vb[row * KS + c], &qkv[base + 2048]);
        }
        cp_commit();
    };

    // group0: Q(128x64) + KV(0); group1: KV(1)
#pragma unroll
    for (int i = 0; i < 8; i++) {
        int e = tid + 128 * i;
        int row = e >> 3, c = (e & 7) * 8;
        cp16(&Qs[row * KS + c], &qkv[(size_t)(q0 + row) * QKV_N + h * 64 + c]);
    }
    load_kv(0, 0);
    load_kv(1, 1);

    float oacc[2][8][4];
#pragma unroll
    for (int hh = 0; hh < 2; hh++)
#pragma unroll
        for (int a = 0; a < 8; a++)
#pragma unroll
            for (int c = 0; c < 4; c++) oacc[hh][a][c] = 0.f;
    float lsum[2][2] = {{0.f, 0.f}, {0.f, 0.f}};

    for (int kb = 0; kb < nkb; kb++) {
        const int s = kb % 3;
        if (kb < nkb - 1) cp_wait<1>(); else cp_wait<0>();
        __syncthreads();
        if (kb + 2 < nkb) load_kv(kb + 2, (kb + 2) % 3);

        const uint32_t koff = sbase + (uint32_t)(128 * KS + s * KVSTG) * 2;
        const uint32_t voff = koff + (uint32_t)(64 * KS) * 2;

        // ---- S = Q K^T (Q pre-scaled) ----
        float sacc[2][8][4];
#pragma unroll
        for (int hh = 0; hh < 2; hh++)
#pragma unroll
            for (int a = 0; a < 8; a++)
#pragma unroll
                for (int c = 0; c < 4; c++) sacc[hh][a][c] = 0.f;

#pragma unroll
        for (int ks = 0; ks < 4; ks++) {
            uint32_t aq[2][4];
            ldsm4(aq[0], qoff + ((mrow + lr8) * KS + ks * 16 + lc8) * 2);
            ldsm4(aq[1], qoff + ((mrow + 16 + lr8) * KS + ks * 16 + lc8) * 2);
#pragma unroll
            for (int nh = 0; nh < 4; nh++) {
                uint32_t bf[4];
                ldsm4(bf, koff + ((nh * 16 + bn8) * KS + ks * 16 + bk8) * 2);
#pragma unroll
                for (int hh = 0; hh < 2; hh++) {
                    mma16(sacc[hh][nh * 2 + 0], aq[hh], bf[0], bf[1]);
                    mma16(sacc[hh][nh * 2 + 1], aq[hh], bf[2], bf[3]);
                }
            }
        }

        // ---- p = ex2(s*log2e - 10*log2e), clamped + masked ----
        const int k0 = kb * 64;
        const bool diag = (kb >= 2 * qb);
        const float L2E = 1.4426950408889634f;
        const float BIA = -14.426950408889634f;   // -10*log2e
#pragma unroll
        for (int hh = 0; hh < 2; hh++) {
#pragma unroll
            for (int nt = 0; nt < 8; nt++) {
#pragma unroll
                for (int e = 0; e < 4; e++) {
                    int row = q0 + mrow + hh * 16 + g + ((e >> 1) << 3);
                    int col = k0 + nt * 8 + 2 * tig + (e & 1);
                    float sv = fminf(fmaxf(sacc[hh][nt][e], -10.f), 10.f);
                    float p = ex2(fmaf(sv, L2E, BIA));
                    if (diag && col > row) p = 0.f;
                    lsum[hh][e >> 1] += p;
                    sacc[hh][nt][e] = p;
                }
            }
        }

        // ---- O += P V (C-frag == A-frag) ----
#pragma unroll
        for (int ksp = 0; ksp < 4; ksp++) {
            uint32_t ap[2][4];
#pragma unroll
            for (int hh = 0; hh < 2; hh++) {
                ap[hh][0] = pack2(sacc[hh][2 * ksp][0], sacc[hh][2 * ksp][1]);
                ap[hh][1] = pack2(sacc[hh][2 * ksp][2], sacc[hh][2 * ksp][3]);
                ap[hh][2] = pack2(sacc[hh][2 * ksp + 1][0], sacc[hh][2 * ksp + 1][1]);
                ap[hh][3] = pack2(sacc[hh][2 * ksp + 1][2], sacc[hh][2 * ksp + 1][3]);
            }
#pragma unroll
            for (int dh = 0; dh < 4; dh++) {
                uint32_t bf[4];
                ldsm4t(bf, voff + ((ksp * 16 + lr8) * KS + dh * 16 + lc8) * 2);
#pragma unroll
                for (int hh = 0; hh < 2; hh++) {
                    mma16(oacc[hh][dh * 2 + 0], ap[hh], bf[0], bf[1]);
                    mma16(oacc[hh][dh * 2 + 1], ap[hh], bf[2], bf[3]);
                }
            }
        }
    }

    // ---- quad row-sum reduction, normalize, fp16 store ----
#pragma unroll
    for (int hh = 0; hh < 2; hh++)
#pragma unroll
        for (int e = 0; e < 2; e++) {
            lsum[hh][e] += __shfl_xor_sync(0xffffffffu, lsum[hh][e], 1);
            lsum[hh][e] += __shfl_xor_sync(0xffffffffu, lsum[hh][e], 2);
        }

#pragma unroll
    for (int hh = 0; hh < 2; hh++) {
        float inv0 = 1.f / lsum[hh][0];
        float inv1 = 1.f / lsum[hh][1];
#pragma unroll
        for (int nt = 0; nt < 8; nt++) {
            int col = h * 64 + nt * 8 + 2 * tig;
            int row0 = q0 + mrow + hh * 16 + g;
            *(uint32_t*)&outp[(size_t)row0 * D_MODEL + col] =
                pack2(oacc[hh][nt][0] * inv0, oacc[hh][nt][1] * inv0);
            *(uint32_t*)&outp[(size_t)(row0 + 8) * D_MODEL + col] =
                pack2(oacc[hh][nt][2] * inv1, oacc[hh][nt][3] * inv1);
        }
    }
}

// ---------------------------------------------------------------------------
// Launch
// ---------------------------------------------------------------------------
extern "C" void kernel_launch(void* const* d_in, const int* in_sizes, int n_in,
                              void* d_out, int out_size) {
    const float* x    = (const float*)d_in[0];   // [4096,1024]
    const float* Wqkv = (const float*)d_in[1];   // [3072,1024]
    const float* Wout = (const float*)d_in[2];   // [1024,1024]
    float* out = (float*)d_out;                  // [4096,1024]

    __half *qkvh, *attnh, *xh, *wqkvh, *wouth;
    cudaGetSymbolAddress((void**)&qkvh, g_qkvh);
    cudaGetSymbolAddress((void**)&attnh, g_attnh);
    cudaGetSymbolAddress((void**)&xh, g_xh);
    cudaGetSymbolAddress((void**)&wqkvh, g_wqkvh);
    cudaGetSymbolAddress((void**)&wouth, g_wouth);

    cudaFuncSetAttribute(gemm_h<true>, cudaFuncAttributeMaxDynamicSharedMemorySize, GEMM_SMEM);
    cudaFuncSetAttribute(gemm_h<false>, cudaFuncAttributeMaxDynamicSharedMemorySize, GEMM_SMEM);
    cudaFuncSetAttribute(attn_h, cudaFuncAttributeMaxDynamicSharedMemorySize, ATT_SMEM);

    // 0) all inputs -> fp16 (single launch)
    const int na = T_TOK * D_MODEL / 4, nb = QKV_N * D_MODEL / 4, nc = D_MODEL * D_MODEL / 4;
    round_all<<<(na + nb + nc + 255) / 256, 256>>>(
        (const float4*)x, (uint2*)xh, na,
        (const float4*)Wqkv, (uint2*)wqkvh, nb,
        (const float4*)Wout, (uint2*)wouth, nc);

    // 1) QKV projection (Q block pre-scaled by 1/8 in epilogue)
    gemm_h<true><<<dim3(QKV_N / 128, T_TOK / 128), 256, GEMM_SMEM>>>(
        xh, wqkvh, qkvh, T_TOK, QKV_N, D_MODEL);

    // 2) causal clamped attention
    attn_h<<<dim3(T_TOK / 128, NH), 128, ATT_SMEM>>>(qkvh, attnh);

    // 3) output projection (fp32 out)
    gemm_h<false><<<dim3(D_MODEL / 128, T_TOK / 128), 256, GEMM_SMEM>>>(
        attnh, wouth, out, T_TOK, D_MODEL, D_MODEL);
}

// round 11
// speedup vs baseline: 2.5453x; 1.0440x over previous
#include <cuda_runtime.h>
#include <cuda_fp16.h>
#include <cstdint>

#define T_TOK 4096
#define D_MODEL 1024
#define NH 16
#define QKV_N 3072

// Scratch (__device__ globals per allocation rules)
__device__ __half g_qkvh[T_TOK * QKV_N];     // q(prescaled)|k|v
__device__ __half g_attnh[T_TOK * D_MODEL];  // attention out
__device__ __half g_xh[T_TOK * D_MODEL];
__device__ __half g_wqkvh[QKV_N * D_MODEL];
__device__ __half g_wouth[D_MODEL * D_MODEL];

// ---------------------------------------------------------------------------
// helpers
// ---------------------------------------------------------------------------
__device__ __forceinline__ void cp16(void* smem, const void* gmem) {
    uint32_t s = (uint32_t)__cvta_generic_to_shared(smem);
    asm volatile("cp.async.cg.shared.global [%0], [%1], 16;" :: "r"(s), "l"(gmem));
}
__device__ __forceinline__ void cp_commit() { asm volatile("cp.async.commit_group;"); }
template <int N> __device__ __forceinline__ void cp_wait() {
    asm volatile("cp.async.wait_group %0;" :: "n"(N));
}
__device__ __forceinline__ uint32_t pack2(float a, float b) {
    __half2 h = __floats2half2_rn(a, b);   // a -> low half
    return *reinterpret_cast<uint32_t*>(&h);
}
__device__ __forceinline__ float ex2(float x) {
    float r; asm("ex2.approx.ftz.f32 %0, %1;" : "=f"(r) : "f"(x)); return r;
}
__device__ __forceinline__ void ldsm4(uint32_t* r, uint32_t addr) {
    asm volatile("ldmatrix.sync.aligned.m8n8.x4.shared.b16 {%0,%1,%2,%3}, [%4];"
                 : "=r"(r[0]), "=r"(r[1]), "=r"(r[2]), "=r"(r[3]) : "r"(addr));
}
__device__ __forceinline__ void ldsm4t(uint32_t* r, uint32_t addr) {
    asm volatile("ldmatrix.sync.aligned.m8n8.x4.trans.shared.b16 {%0,%1,%2,%3}, [%4];"
                 : "=r"(r[0]), "=r"(r[1]), "=r"(r[2]), "=r"(r[3]) : "r"(addr));
}
__device__ __forceinline__ void mma16(float* c, const uint32_t* a, uint32_t b0, uint32_t b1) {
    asm("mma.sync.aligned.m16n8k16.row.col.f32.f16.f16.f32 "
        "{%0,%1,%2,%3}, {%4,%5,%6,%7}, {%8,%9}, {%0,%1,%2,%3};"
        : "+f"(c[0]), "+f"(c[1]), "+f"(c[2]), "+f"(c[3])
        : "r"(a[0]), "r"(a[1]), "r"(a[2]), "r"(a[3]), "r"(b0), "r"(b1));
}

// ---------------------------------------------------------------------------
// fused fp32 -> fp16 rounding for all three inputs (one launch)
// ---------------------------------------------------------------------------
__global__ void round_all(const float4* __restrict__ a, uint2* __restrict__ ao, int na,
                          const float4* __restrict__ b, uint2* __restrict__ bo, int nb,
                          const float4* __restrict__ c, uint2* __restrict__ co, int nc) {
    int i = blockIdx.x * blockDim.x + threadIdx.x;
    const float4* src;
    uint2* dst;
    if (i < na) { src = a + i; dst = ao + i; }
    else if (i < na + nb) { src = b + (i - na); dst = bo + (i - na); }
    else if (i < na + nb + nc) { src = c + (i - na - nb); dst = co + (i - na - nb); }
    else return;
    float4 v = *src;
    *dst = make_uint2(pack2(v.x, v.y), pack2(v.z, v.w));
}

// ---------------------------------------------------------------------------
// fp16 tensor-core GEMM (NT), 3-stage cp.async pipeline (unchanged).
// ---------------------------------------------------------------------------
#define SAH 40
#define STG (2 * 128 * SAH)
#define GEMM_SMEM (3 * STG * 2)

template <bool HALF_OUT>
__global__ __launch_bounds__(256, 2) void gemm_h(const __half* __restrict__ A,
                                                 const __half* __restrict__ B,
                                                 void* __restrict__ Cv,
                                                 int M, int N, int K) {
    extern __shared__ __half smh[];
    const uint32_t sbase = (uint32_t)__cvta_generic_to_shared(smh);

    const int tid = threadIdx.x;
    const int wid = tid >> 5, lane = tid & 31;
    const int g = lane >> 2, tig = lane & 3;
    const int mW = (wid >> 2) * 64, nW = (wid & 3) * 32;
    const int by = blockIdx.y * 128, bx = blockIdx.x * 128;

    const int lr8 = (lane & 7) + ((lane >> 3) & 1) * 8;
    const int lc8 = (lane >> 4) * 8;
    const int bn8 = (lane & 7) + (lane >> 4) * 8;
    const int bk8 = ((lane >> 3) & 1) * 8;

    float acc[4][4][4];
#pragma unroll
    for (int a = 0; a < 4; a++)
#pragma unroll
        for (int b = 0; b < 4; b++)
#pragma unroll
            for (int c = 0; c < 4; c++) acc[a][b][c] = 0.f;

    const int nkt = K / 32;

    auto fill = [&](int kt, int s) {
        const __half* Ag = A + (size_t)by * K + kt * 32;
        const __half* Bg = B + (size_t)bx * K + kt * 32;
        __half* Ab = smh + s * STG;
        __half* Bb = Ab + 128 * SAH;
#pragma unroll
        for (int i = 0; i < 2; i++) {
            int e = tid + 256 * i;
            int row = e >> 2, c = (e & 3) * 8;
            cp16(&Ab[row * SAH + c], Ag + (size_t)row * K + c);
            cp16(&Bb[row * SAH + c], Bg + (size_t)row * K + c);
        }
        cp_commit();
    };

    fill(0, 0);
    fill(1, 1);
    for (int kt = 0; kt < nkt; kt++) {
        const int s = kt % 3;
        if (kt < nkt - 1) cp_wait<1>(); else cp_wait<0>();
        __syncthreads();
        if (kt + 2 < nkt) fill(kt + 2, (kt + 2) % 3);

        const uint32_t aoff = sbase + (uint32_t)(s * STG) * 2;
        const uint32_t boff = aoff + (uint32_t)(128 * SAH) * 2;

#pragma unroll
        for (int ks = 0; ks < 2; ks++) {
            uint32_t af[4][4], bf[2][4];
#pragma unroll
            for (int mt = 0; mt < 4; mt++) {
                int r = mW + mt * 16 + lr8;
                int c = ks * 16 + lc8;
                ldsm4(af[mt], aoff + (r * SAH + c) * 2);
            }
#pragma unroll
            for (int nh = 0; nh < 2; nh++) {
                int r = nW + nh * 16 + bn8;
                int c = ks * 16 + bk8;
                ldsm4(bf[nh], boff + (r * SAH + c) * 2);
            }
#pragma unroll
            for (int mt = 0; mt < 4; mt++)
#pragma unroll
                for (int nt = 0; nt < 4; nt++)
                    mma16(acc[mt][nt], af[mt], bf[nt >> 1][(nt & 1) * 2],
                          bf[nt >> 1][(nt & 1) * 2 + 1]);
        }
    }

    const float sc = (HALF_OUT && bx < 1024) ? 0.125f : 1.f;
#pragma unroll
    for (int mt = 0; mt < 4; mt++) {
#pragma unroll
        for (int nt = 0; nt < 4; nt++) {
            int row = by + mW + mt * 16 + g;
            int col = bx + nW + nt * 8 + tig * 2;
            if (HALF_OUT) {
                __half* C = (__half*)Cv;
                *(uint32_t*)&C[(size_t)row * N + col] =
                    pack2(acc[mt][nt][0] * sc, acc[mt][nt][1] * sc);
                *(uint32_t*)&C[(size_t)(row + 8) * N + col] =
                    pack2(acc[mt][nt][2] * sc, acc[mt][nt][3] * sc);
            } else {
                float* C = (float*)Cv;
                *(float2*)&C[(size_t)row * N + col] = make_float2(acc[mt][nt][0], acc[mt][nt][1]);
                *(float2*)&C[(size_t)(row + 8) * N + col] = make_float2(acc[mt][nt][2], acc[mt][nt][3]);
            }
        }
    }
}

// ---------------------------------------------------------------------------
// fp16 causal attention: 4 warps x 32 Q-rows, 3-stage K/V pipeline.
// exp computed in fp32 (ex2.approx.ftz.f32, proven accurate), then rounded
// to fp16 P-fragments directly. Causal mask = AND on packed pair.
// Row sums via ones-mma (same fp16 P for numerator and denominator).
// a = clamp(s*log2e - 10*log2e, -20*log2e, 0) == clamp(s,-10,10)-10 in log2.
// ---------------------------------------------------------------------------
#define KS 72
#define KVSTG (2 * 64 * KS)
#define ATT_SMEM ((128 * KS + 3 * KVSTG) * 2)   // 73728 B

#define ONES_H2 0x3C003C00u

__global__ __launch_bounds__(128, 3) void attn_h(const __half* __restrict__ qkv,
                                                 __half* __restrict__ outp) {
    extern __shared__ __half smh[];
    __half* Qs = smh;
    const uint32_t sbase = (uint32_t)__cvta_generic_to_shared(smh);
    const uint32_t qoff = sbase;

    const int h = blockIdx.y;
    const int qb = gridDim.x - 1 - blockIdx.x;         // heavy tiles first
    const int q0 = qb * 128;
    const int tid = threadIdx.x;
    const int wid = tid >> 5, lane = tid & 31;
    const int g = lane >> 2, tig = lane & 3;
    const int mrow = wid * 32;
    const int nkb = 2 * qb + 2;

    const int lr8 = (lane & 7) + ((lane >> 3) & 1) * 8;
    const int lc8 = (lane >> 4) * 8;
    const int bn8 = (lane & 7) + (lane >> 4) * 8;
    const int bk8 = ((lane >> 3) & 1) * 8;

    auto load_kv = [&](int kb, int s) {
        const int k0 = kb * 64;
        __half* Kb = smh + 128 * KS + s * KVSTG;
        __half* Vb = Kb + 64 * KS;
#pragma unroll
        for (int i = 0; i < 4; i++) {
            int e = tid + 128 * i;
            int row = e >> 3, c = (e & 7) * 8;
            size_t base = (size_t)(k0 + row) * QKV_N + h * 64 + c;
            cp16(&Kb[row * KS + c], &qkv[base + 1024]);
            cp16(&Vb[row * KS + c], &qkv[base + 2048]);
        }
        cp_commit();
    };

#pragma unroll
    for (int i = 0; i < 8; i++) {
        int e = tid + 128 * i;
        int row = e >> 3, c = (e & 7) * 8;
        cp16(&Qs[row * KS + c], &qkv[(size_t)(q0 + row) * QKV_N + h * 64 + c]);
    }
    load_kv(0, 0);
    load_kv(1, 1);

    float oacc[2][8][4];
#pragma unroll
    for (int hh = 0; hh < 2; hh++)
#pragma unroll
        for (int a = 0; a < 8; a++)
#pragma unroll
            for (int c = 0; c < 4; c++) oacc[hh][a][c] = 0.f;
    float lacc[2][4];
#pragma unroll
    for (int hh = 0; hh < 2; hh++)
#pragma unroll
        for (int c = 0; c < 4; c++) lacc[hh][c] = 0.f;

    const float L2E = 1.4426950408889634f;
    const float BIA = -14.4269504089f;    // -10*log2e
    const float AMIN = -28.8539008178f;   // -20*log2e (s = -10)

    for (int kb = 0; kb < nkb; kb++) {
        const int s = kb % 3;
        if (kb < nkb - 1) cp_wait<1>(); else cp_wait<0>();
        __syncthreads();
        if (kb + 2 < nkb) load_kv(kb + 2, (kb + 2) % 3);

        const uint32_t koff = sbase + (uint32_t)(128 * KS + s * KVSTG) * 2;
        const uint32_t voff = koff + (uint32_t)(64 * KS) * 2;

        // ---- S = Q K^T (Q pre-scaled by 1/8) ----
        float sacc[2][8][4];
#pragma unroll
        for (int hh = 0; hh < 2; hh++)
#pragma unroll
            for (int a = 0; a < 8; a++)
#pragma unroll
                for (int c = 0; c < 4; c++) sacc[hh][a][c] = 0.f;

#pragma unroll
        for (int ks = 0; ks < 4; ks++) {
            uint32_t aq[2][4];
            ldsm4(aq[0], qoff + ((mrow + lr8) * KS + ks * 16 + lc8) * 2);
            ldsm4(aq[1], qoff + ((mrow + 16 + lr8) * KS + ks * 16 + lc8) * 2);
#pragma unroll
            for (int nh = 0; nh < 4; nh++) {
                uint32_t bf[4];
                ldsm4(bf, koff + ((nh * 16 + bn8) * KS + ks * 16 + bk8) * 2);
#pragma unroll
                for (int hh = 0; hh < 2; hh++) {
                    mma16(sacc[hh][nh * 2 + 0], aq[hh], bf[0], bf[1]);
                    mma16(sacc[hh][nh * 2 + 1], aq[hh], bf[2], bf[3]);
                }
            }
        }

        // ---- softmax numerator: fp32 exp, fp16 pack; mask on packed pair ----
        const int k0 = kb * 64;
        const bool diag = (kb >= 2 * qb);
        uint32_t pfrag[2][4][4];
#pragma unroll
        for (int hh = 0; hh < 2; hh++) {
#pragma unroll
            for (int nt = 0; nt < 8; nt++) {
                float a0 = fmaxf(fmaf(sacc[hh][nt][0], L2E, BIA), AMIN);
                float a1 = fmaxf(fmaf(sacc[hh][nt][1], L2E, BIA), AMIN);
                float a2 = fmaxf(fmaf(sacc[hh][nt][2], L2E, BIA), AMIN);
                float a3 = fmaxf(fmaf(sacc[hh][nt][3], L2E, BIA), AMIN);
                a0 = fminf(a0, 0.f); a1 = fminf(a1, 0.f);
                a2 = fminf(a2, 0.f); a3 = fminf(a3, 0.f);
                uint32_t p01 = pack2(ex2(a0), ex2(a1));
                uint32_t p23 = pack2(ex2(a2), ex2(a3));
                if (diag) {
                    int row0 = q0 + mrow + hh * 16 + g;
                    int c0 = k0 + nt * 8 + 2 * tig;
                    p01 &= (c0 + 1 <= row0) ? 0xFFFFFFFFu
                                            : ((c0 <= row0) ? 0x0000FFFFu : 0u);
                    p23 &= (c0 + 1 <= row0 + 8) ? 0xFFFFFFFFu
                                                : ((c0 <= row0 + 8) ? 0x0000FFFFu : 0u);
                }
                pfrag[hh][nt >> 1][(nt & 1) * 2 + 0] = p01;
                pfrag[hh][nt >> 1][(nt & 1) * 2 + 1] = p23;
            }
        }

        // ---- O += P V ; row sums via ones-mma ----
#pragma unroll
        for (int ksp = 0; ksp < 4; ksp++) {
#pragma unroll
            for (int dh = 0; dh < 4; dh++) {
                uint32_t bf[4];
                ldsm4t(bf, voff + ((ksp * 16 + lr8) * KS + dh * 16 + lc8) * 2);
#pragma unroll
                for (int hh = 0; hh < 2; hh++) {
                    mma16(oacc[hh][dh * 2 + 0], pfrag[hh][ksp], bf[0], bf[1]);
                    mma16(oacc[hh][dh * 2 + 1], pfrag[hh][ksp], bf[2], bf[3]);
                }
            }
#pragma unroll
            for (int hh = 0; hh < 2; hh++)
                mma16(lacc[hh], pfrag[hh][ksp], ONES_H2, ONES_H2);
        }
    }

    // ---- normalize (lacc[.][0] = row g sum, lacc[.][2] = row g+8 sum) ----
#pragma unroll
    for (int hh = 0; hh < 2; hh++) {
        float inv0 = 1.f / lacc[hh][0];
        float inv1 = 1.f / lacc[hh][2];
#pragma unroll
        for (int nt = 0; nt < 8; nt++) {
            int col = h * 64 + nt * 8 + 2 * tig;
            int row0 = q0 + mrow + hh * 16 + g;
            *(uint32_t*)&outp[(size_t)row0 * D_MODEL + col] =
                pack2(oacc[hh][nt][0] * inv0, oacc[hh][nt][1] * inv0);
            *(uint32_t*)&outp[(size_t)(row0 + 8) * D_MODEL + col] =
                pack2(oacc[hh][nt][2] * inv1, oacc[hh][nt][3] * inv1);
        }
    }
}

// ---------------------------------------------------------------------------
// Launch
// ---------------------------------------------------------------------------
extern "C" void kernel_launch(void* const* d_in, const int* in_sizes, int n_in,
                              void* d_out, int out_size) {
    const float* x    = (const float*)d_in[0];   // [4096,1024]
    const float* Wqkv = (const float*)d_in[1];   // [3072,1024]
    const float* Wout = (const float*)d_in[2];   // [1024,1024]
    float* out = (float*)d_out;                  // [4096,1024]

    __half *qkvh, *attnh, *xh, *wqkvh, *wouth;
    cudaGetSymbolAddress((void**)&qkvh, g_qkvh);
    cudaGetSymbolAddress((void**)&attnh, g_attnh);
    cudaGetSymbolAddress((void**)&xh, g_xh);
    cudaGetSymbolAddress((void**)&wqkvh, g_wqkvh);
    cudaGetSymbolAddress((void**)&wouth, g_wouth);

    cudaFuncSetAttribute(gemm_h<true>, cudaFuncAttributeMaxDynamicSharedMemorySize, GEMM_SMEM);
    cudaFuncSetAttribute(gemm_h<false>, cudaFuncAttributeMaxDynamicSharedMemorySize, GEMM_SMEM);
    cudaFuncSetAttribute(attn_h, cudaFuncAttributeMaxDynamicSharedMemorySize, ATT_SMEM);

    // 0) all inputs -> fp16 (single launch)
    const int na = T_TOK * D_MODEL / 4, nb = QKV_N * D_MODEL / 4, nc = D_MODEL * D_MODEL / 4;
    round_all<<<(na + nb + nc + 255) / 256, 256>>>(
        (const float4*)x, (uint2*)xh, na,
        (const float4*)Wqkv, (uint2*)wqkvh, nb,
        (const float4*)Wout, (uint2*)wouth, nc);

    // 1) QKV projection (Q block pre-scaled by 1/8 in epilogue)
    gemm_h<true><<<dim3(QKV_N / 128, T_TOK / 128), 256, GEMM_SMEM>>>(
        xh, wqkvh, qkvh, T_TOK, QKV_N, D_MODEL);

    // 2) causal clamped attention
    attn_h<<<dim3(T_TOK / 128, NH), 128, ATT_SMEM>>>(qkvh, attnh);

    // 3) output projection (fp32 out)
    gemm_h<false><<<dim3(D_MODEL / 128, T_TOK / 128), 256, GEMM_SMEM>>>(
        attnh, wouth, out, T_TOK, D_MODEL, D_MODEL);
}